// round 5
// baseline (speedup 1.0000x reference)
#include <cuda_runtime.h>
#include <cuda_fp16.h>
#include <cstdint>

#define GRIDS 64
#define GP    65            // GRIDS + 1
#define ODIM  128
#define PDIM  64            // INPUT_DIM / 2
#define BATCH 16384
#define CELLS (GP * GP)     // 4225
#define BT    32            // batch tile per block

// fp16 transposed table, layout [cell][p][o]  (16KB contiguous per cell)
__device__ __half g_fpt[(size_t)CELLS * PDIM * ODIM];   // ~69 MB

// ---------------------------------------------------------------------------
// Kernel 1: transpose + fp32->fp16 convert.
// fp[cell][o][p] (p contiguous)  ->  g_fpt[cell][p][o] (o contiguous)
// One block per cell: 32KB coalesced read, 16KB fully contiguous write.
// ---------------------------------------------------------------------------
__global__ __launch_bounds__(256) void kan_transpose(const float* __restrict__ fp) {
    __shared__ float tile[ODIM * (PDIM + 1)];   // [o][p], pad 65
    const int cell = blockIdx.x;
    const float4* src = reinterpret_cast<const float4*>(fp + (size_t)cell * (ODIM * PDIM));

    // Read: 2048 float4 (o-major, p contiguous)
    for (int idx = threadIdx.x; idx < (ODIM * PDIM) / 4; idx += 256) {
        int o  = idx >> 4;          // 16 float4 per o-row
        int p4 = (idx & 15) << 2;
        float4 v = src[idx];
        float* row = &tile[o * (PDIM + 1) + p4];
        row[0] = v.x; row[1] = v.y; row[2] = v.z; row[3] = v.w;
    }
    __syncthreads();

    // Write: uint4 = 8 halves along o; destination fully contiguous per cell.
    uint4* dst = reinterpret_cast<uint4*>(g_fpt + (size_t)cell * (PDIM * ODIM));
    for (int idx = threadIdx.x; idx < (ODIM * PDIM) / 8; idx += 256) {
        int p  = idx >> 4;          // 16 uint4 per p-row
        int o8 = (idx & 15) << 3;
        uint4 v;
        unsigned* u = &v.x;
#pragma unroll
        for (int k = 0; k < 4; ++k) {
            float lo = tile[(o8 + 2 * k)     * (PDIM + 1) + p];
            float hi = tile[(o8 + 2 * k + 1) * (PDIM + 1) + p];
            __half2 h = __floats2half2_rn(lo, hi);
            u[k] = *reinterpret_cast<unsigned*>(&h);
        }
        dst[idx] = v;
    }
}

// ---------------------------------------------------------------------------
// Kernel 2: main gather + bilinear reduction.
// Block: 512 threads = 16 o-groups (8 outputs each) x 32 batch columns.
// Prologue precomputes cell index + 4 broadcast half2 weights per (p,b);
// main loop: 2 LDS + 4 LDG.128 + HFMA2 chain + fp32 accumulate. No barriers.
// ---------------------------------------------------------------------------
__global__ __launch_bounds__(512) void kan_main(const float* __restrict__ x,
                                                const float* __restrict__ borders,
                                                const float* __restrict__ invlen,
                                                float* __restrict__ out) {
    __shared__ float sb[GP];
    __shared__ float sl[GRIDS];
    __shared__ int   s_cell[PDIM][BT];
    __shared__ uint4 s_wq[PDIM][BT];     // packed broadcast half2 weights
    __shared__ float so[ODIM][BT + 1];   // epilogue transpose buffer

    const int t  = threadIdx.x;
    const int og = t & 15;     // o-group: owns outputs og*8 .. og*8+7
    const int bi = t >> 4;     // batch index within tile, 0..31
    const int b0 = blockIdx.x * BT;

    if (t < GP)                 sb[t] = borders[t];
    else if (t < GP + GRIDS)    sl[t - GP] = invlen[t - GP];
    __syncthreads();

    // Prologue: indices + packed interpolation weights for all (p, b).
    for (int i = t; i < PDIM * BT; i += 512) {
        int p = i >> 5;        // /32
        int b = i & 31;
        float v1 = x[(size_t)(2 * p) * BATCH + b0 + b];
        float v2 = x[(size_t)(2 * p + 1) * BATCH + b0 + b];

        float e1 = expf(-fabsf(v1));
        float c1 = (v1 > 0.f) ? (1.f - 0.5f * e1) : (0.5f * e1);
        int i1 = (int)(c1 * (float)GRIDS);
        i1 = i1 < 0 ? 0 : (i1 > GRIDS - 1 ? GRIDS - 1 : i1);

        float e2 = expf(-fabsf(v2));
        float c2 = (v2 > 0.f) ? (1.f - 0.5f * e2) : (0.5f * e2);
        int i2 = (int)(c2 * (float)GRIDS);
        i2 = i2 < 0 ? 0 : (i2 > GRIDS - 1 ? GRIDS - 1 : i2);

        float d1 = (v1 - sb[i1]) * sl[i1];
        float d2 = (v2 - sb[i2]) * sl[i2];
        float w11 = d1 * d2;
        float w10 = d1 - w11;
        float w01 = d2 - w11;
        float w00 = 1.f - d1 - w01;

        s_cell[p][b] = i1 * GP + i2;
        __half2 h00 = __float2half2_rn(w00);
        __half2 h01 = __float2half2_rn(w01);
        __half2 h10 = __float2half2_rn(w10);
        __half2 h11 = __float2half2_rn(w11);
        uint4 wq;
        wq.x = *reinterpret_cast<unsigned*>(&h00);
        wq.y = *reinterpret_cast<unsigned*>(&h01);
        wq.z = *reinterpret_cast<unsigned*>(&h10);
        wq.w = *reinterpret_cast<unsigned*>(&h11);
        s_wq[p][b] = wq;
    }
    __syncthreads();

    float acc[8] = {0.f, 0.f, 0.f, 0.f, 0.f, 0.f, 0.f, 0.f};
    const __half* __restrict__ tab = g_fpt;
    const int oofs = og * 8;

#pragma unroll 2
    for (int p = 0; p < PDIM; ++p) {
        const int   c  = s_cell[p][bi];
        const uint4 wq = s_wq[p][bi];
        const __half2 h00 = *reinterpret_cast<const __half2*>(&wq.x);
        const __half2 h01 = *reinterpret_cast<const __half2*>(&wq.y);
        const __half2 h10 = *reinterpret_cast<const __half2*>(&wq.z);
        const __half2 h11 = *reinterpret_cast<const __half2*>(&wq.w);

        // layout [cell][p][o]
        const __half* base = tab + ((size_t)c * PDIM + p) * ODIM + oofs;
        uint4 a0 = *reinterpret_cast<const uint4*>(base);                          // (i1,   i2  )
        uint4 a1 = *reinterpret_cast<const uint4*>(base + PDIM * ODIM);            // (i1,   i2+1)
        uint4 a2 = *reinterpret_cast<const uint4*>(base + GP * PDIM * ODIM);       // (i1+1, i2  )
        uint4 a3 = *reinterpret_cast<const uint4*>(base + (GP + 1) * PDIM * ODIM); // (i1+1, i2+1)

        const unsigned* u0 = &a0.x;
        const unsigned* u1 = &a1.x;
        const unsigned* u2 = &a2.x;
        const unsigned* u3 = &a3.x;
#pragma unroll
        for (int j = 0; j < 4; ++j) {
            __half2 v0 = *reinterpret_cast<const __half2*>(&u0[j]);
            __half2 v1 = *reinterpret_cast<const __half2*>(&u1[j]);
            __half2 v2 = *reinterpret_cast<const __half2*>(&u2[j]);
            __half2 v3 = *reinterpret_cast<const __half2*>(&u3[j]);
            __half2 s = __hmul2(h00, v0);
            s = __hfma2(h01, v1, s);
            s = __hfma2(h10, v2, s);
            s = __hfma2(h11, v3, s);
            float2 f = __half22float2(s);
            acc[2 * j]     += f.x;
            acc[2 * j + 1] += f.y;
        }
    }

    // Epilogue: transpose through smem for coalesced 128B row stores.
    __syncthreads();
#pragma unroll
    for (int k = 0; k < 8; ++k) so[oofs + k][bi] = acc[k];
    __syncthreads();
    for (int idx = t; idx < ODIM * BT; idx += 512) {
        int o = idx >> 5;   // /32
        int j = idx & 31;
        out[(size_t)o * BATCH + b0 + j] = so[o][j];
    }
}

extern "C" void kernel_launch(void* const* d_in, const int* in_sizes, int n_in,
                              void* d_out, int out_size) {
    const float* x       = (const float*)d_in[0];
    const float* fp      = (const float*)d_in[1];
    const float* borders = (const float*)d_in[2];
    const float* invlen  = (const float*)d_in[3];
    float* out = (float*)d_out;

    kan_transpose<<<CELLS, 256>>>(fp);
    kan_main<<<BATCH / BT, 512>>>(x, borders, invlen, out);
}

// round 6
// speedup vs baseline: 1.1703x; 1.1703x over previous
#include <cuda_runtime.h>
#include <cuda_fp16.h>
#include <cstdint>

#define GRIDS 64
#define GP    65            // GRIDS + 1
#define ODIM  128
#define PDIM  64            // INPUT_DIM / 2
#define BATCH 16384
#define CELLS (GP * GP)     // 4225
#define BT    32            // batch tile per block

// fp16 transposed table: fp_t[p][cell][o], cell = ia*65 + ib   (R4 layout)
__device__ __half g_fpt[(size_t)PDIM * CELLS * ODIM];   // ~69 MB

// ---------------------------------------------------------------------------
// Kernel 1: transpose + fp32->fp16 convert (exact R4 version).
// ---------------------------------------------------------------------------
__global__ __launch_bounds__(256) void kan_transpose(const float* __restrict__ fp) {
    __shared__ float tile[ODIM * (PDIM + 1)];   // [o][p], pad 65
    const int cell = blockIdx.x;
    const float4* src = reinterpret_cast<const float4*>(fp + (size_t)cell * (ODIM * PDIM));

    for (int idx = threadIdx.x; idx < (ODIM * PDIM) / 4; idx += 256) {
        int o  = idx >> 4;
        int p4 = (idx & 15) << 2;
        float4 v = src[idx];
        float* row = &tile[o * (PDIM + 1) + p4];
        row[0] = v.x; row[1] = v.y; row[2] = v.z; row[3] = v.w;
    }
    __syncthreads();

    __half2* dst2 = reinterpret_cast<__half2*>(g_fpt);
    for (int idx = threadIdx.x; idx < (ODIM * PDIM) / 2; idx += 256) {
        int p  = idx >> 6;
        int o2 = idx & 63;
        float lo = tile[(2 * o2) * (PDIM + 1) + p];
        float hi = tile[(2 * o2 + 1) * (PDIM + 1) + p];
        dst2[((size_t)p * CELLS + cell) * (ODIM / 2) + o2] =
            __floats2half2_rn(lo, hi);
    }
}

// ---------------------------------------------------------------------------
// Kernel 2: main gather + bilinear reduction.
// Block: 512 threads = 16 o-groups (8 outputs each) x 32 batch columns.
// Prologue precomputes cell + 4 packed half weights (uint2) per (p,b);
// loop: LDS.32 (cell) + LDS.64 (weights) + 4 LDG.128 + HFMA2 chain.
// ---------------------------------------------------------------------------
__global__ __launch_bounds__(512) void kan_main(const float* __restrict__ x,
                                                const float* __restrict__ borders,
                                                const float* __restrict__ invlen,
                                                float* __restrict__ out) {
    __shared__ float sb[GP];
    __shared__ float sl[GRIDS];
    __shared__ int   s_cell[PDIM][BT];
    __shared__ uint2 s_wq[PDIM][BT];     // 4 packed half weights
    __shared__ float so[ODIM][BT + 1];   // epilogue transpose buffer

    const int t  = threadIdx.x;
    const int og = t & 15;     // o-group: owns outputs og*8 .. og*8+7
    const int bi = t >> 4;     // batch index within tile, 0..31
    const int b0 = blockIdx.x * BT;

    if (t < GP)                 sb[t] = borders[t];
    else if (t < GP + GRIDS)    sl[t - GP] = invlen[t - GP];
    __syncthreads();

    // Prologue: indices + packed interpolation weights for all (p, b).
    for (int i = t; i < PDIM * BT; i += 512) {
        int p = i >> 5;        // /32
        int b = i & 31;
        float v1 = x[(size_t)(2 * p) * BATCH + b0 + b];
        float v2 = x[(size_t)(2 * p + 1) * BATCH + b0 + b];

        float e1 = expf(-fabsf(v1));
        float c1 = (v1 > 0.f) ? (1.f - 0.5f * e1) : (0.5f * e1);
        int i1 = (int)(c1 * (float)GRIDS);
        i1 = i1 < 0 ? 0 : (i1 > GRIDS - 1 ? GRIDS - 1 : i1);

        float e2 = expf(-fabsf(v2));
        float c2 = (v2 > 0.f) ? (1.f - 0.5f * e2) : (0.5f * e2);
        int i2 = (int)(c2 * (float)GRIDS);
        i2 = i2 < 0 ? 0 : (i2 > GRIDS - 1 ? GRIDS - 1 : i2);

        float d1 = (v1 - sb[i1]) * sl[i1];
        float d2 = (v2 - sb[i2]) * sl[i2];
        float w11 = d1 * d2;
        float w10 = d1 - w11;
        float w01 = d2 - w11;
        float w00 = 1.f - d1 - w01;

        s_cell[p][b] = i1 * GP + i2;
        __half2 hA = __floats2half2_rn(w00, w01);   // lanes: (w00, w01)
        __half2 hB = __floats2half2_rn(w10, w11);   // lanes: (w10, w11)
        uint2 wq;
        wq.x = *reinterpret_cast<unsigned*>(&hA);
        wq.y = *reinterpret_cast<unsigned*>(&hB);
        s_wq[p][b] = wq;
    }
    __syncthreads();

    float acc[8] = {0.f, 0.f, 0.f, 0.f, 0.f, 0.f, 0.f, 0.f};
    const __half* __restrict__ tab = g_fpt;
    const int oofs = og * 8;

#pragma unroll 2
    for (int p = 0; p < PDIM; ++p) {
        const int   c  = s_cell[p][bi];
        const uint2 wq = s_wq[p][bi];
        const __half2 hA = *reinterpret_cast<const __half2*>(&wq.x);
        const __half2 hB = *reinterpret_cast<const __half2*>(&wq.y);
        const __half2 h00 = __half2half2(__low2half(hA));
        const __half2 h01 = __half2half2(__high2half(hA));
        const __half2 h10 = __half2half2(__low2half(hB));
        const __half2 h11 = __half2half2(__high2half(hB));

        // layout [p][cell][o]
        const __half* base = tab + ((size_t)p * CELLS + c) * ODIM + oofs;
        uint4 a0 = *reinterpret_cast<const uint4*>(base);                   // (i1,   i2  )
        uint4 a1 = *reinterpret_cast<const uint4*>(base + ODIM);            // (i1,   i2+1)
        uint4 a2 = *reinterpret_cast<const uint4*>(base + GP * ODIM);       // (i1+1, i2  )
        uint4 a3 = *reinterpret_cast<const uint4*>(base + (GP + 1) * ODIM); // (i1+1, i2+1)

        const unsigned* u0 = &a0.x;
        const unsigned* u1 = &a1.x;
        const unsigned* u2 = &a2.x;
        const unsigned* u3 = &a3.x;
#pragma unroll
        for (int j = 0; j < 4; ++j) {
            __half2 v0 = *reinterpret_cast<const __half2*>(&u0[j]);
            __half2 v1 = *reinterpret_cast<const __half2*>(&u1[j]);
            __half2 v2 = *reinterpret_cast<const __half2*>(&u2[j]);
            __half2 v3 = *reinterpret_cast<const __half2*>(&u3[j]);
            __half2 s = __hmul2(h00, v0);
            s = __hfma2(h01, v1, s);
            s = __hfma2(h10, v2, s);
            s = __hfma2(h11, v3, s);
            float2 f = __half22float2(s);
            acc[2 * j]     += f.x;
            acc[2 * j + 1] += f.y;
        }
    }

    // Epilogue: transpose through smem for coalesced 128B row stores.
    __syncthreads();
#pragma unroll
    for (int k = 0; k < 8; ++k) so[oofs + k][bi] = acc[k];
    __syncthreads();
    for (int idx = t; idx < ODIM * BT; idx += 512) {
        int o = idx >> 5;   // /32
        int j = idx & 31;
        out[(size_t)o * BATCH + b0 + j] = so[o][j];
    }
}

extern "C" void kernel_launch(void* const* d_in, const int* in_sizes, int n_in,
                              void* d_out, int out_size) {
    const float* x       = (const float*)d_in[0];
    const float* fp      = (const float*)d_in[1];
    const float* borders = (const float*)d_in[2];
    const float* invlen  = (const float*)d_in[3];
    float* out = (float*)d_out;

    kan_transpose<<<CELLS, 256>>>(fp);
    kan_main<<<BATCH / BT, 512>>>(x, borders, invlen, out);
}

// round 7
// speedup vs baseline: 1.2088x; 1.0329x over previous
#include <cuda_runtime.h>
#include <cuda_fp16.h>
#include <cstdint>

#define GRIDS 64
#define GP    65            // GRIDS + 1
#define ODIM  128
#define PDIM  64            // INPUT_DIM / 2
#define BATCH 16384
#define CELLS (GP * GP)     // 4225
#define BT    32            // batch tile per block

// fp16 transposed table: fp_t[p][cell][o], cell = ia*65 + ib
__device__ __half g_fpt[(size_t)PDIM * CELLS * ODIM];   // ~69 MB

// ---------------------------------------------------------------------------
// Kernel 1: transpose + fp32->fp16 convert.
// smem tile laid out [p][o] (pitch 129) so the write phase reads contiguous
// floats (LDS.128, conflict-free) and stores uint4 (STG.128).
// Output layout identical to R6: g_fpt[p][cell][o].
// ---------------------------------------------------------------------------
__global__ __launch_bounds__(256) void kan_transpose(const float* __restrict__ fp) {
    __shared__ float tile[PDIM][ODIM + 1];   // 64 x 129 floats = 33 KB
    const int cell = blockIdx.x;
    const float4* src = reinterpret_cast<const float4*>(fp + (size_t)cell * (ODIM * PDIM));

    // Read: 2048 float4 (o-major rows, p contiguous) -> tile[p][o]
    for (int idx = threadIdx.x; idx < (ODIM * PDIM) / 4; idx += 256) {
        int o  = idx >> 4;           // 16 float4 per o-row
        int p4 = (idx & 15) << 2;
        float4 v = src[idx];
        tile[p4 + 0][o] = v.x;
        tile[p4 + 1][o] = v.y;
        tile[p4 + 2][o] = v.z;
        tile[p4 + 3][o] = v.w;
    }
    __syncthreads();

    // Write: each thread packs 8 consecutive o into one uint4 store.
    uint4* dst = reinterpret_cast<uint4*>(g_fpt);
    for (int idx = threadIdx.x; idx < (ODIM * PDIM) / 8; idx += 256) {
        int p  = idx >> 4;           // 16 uint4 per (p,cell) row
        int o8 = (idx & 15) << 3;
        uint4 v;
        unsigned* u = &v.x;
#pragma unroll
        for (int k = 0; k < 4; ++k) {
            __half2 h = __floats2half2_rn(tile[p][o8 + 2 * k], tile[p][o8 + 2 * k + 1]);
            u[k] = *reinterpret_cast<unsigned*>(&h);
        }
        dst[((size_t)p * CELLS + cell) * (ODIM / 8) + (o8 >> 3)] = v;
    }
}

// ---------------------------------------------------------------------------
// Kernel 2: main gather + bilinear reduction.
// Block: 512 threads = 16 o-groups (8 outputs each) x 32 batch columns.
// Main loop: 16 groups of 4 p-iterations; each group accumulates in half2
// and flushes once to the fp32 accumulators.
// ---------------------------------------------------------------------------
__global__ __launch_bounds__(512, 2) void kan_main(const float* __restrict__ x,
                                                   const float* __restrict__ borders,
                                                   const float* __restrict__ invlen,
                                                   float* __restrict__ out) {
    __shared__ float sb[GP];
    __shared__ float sl[GRIDS];
    __shared__ int   s_cell[PDIM][BT];
    __shared__ uint2 s_wq[PDIM][BT];     // 4 packed half weights
    __shared__ float so[ODIM][BT + 1];   // epilogue transpose buffer

    const int t  = threadIdx.x;
    const int og = t & 15;     // o-group: owns outputs og*8 .. og*8+7
    const int bi = t >> 4;     // batch index within tile, 0..31
    const int b0 = blockIdx.x * BT;

    if (t < GP)                 sb[t] = borders[t];
    else if (t < GP + GRIDS)    sl[t - GP] = invlen[t - GP];
    __syncthreads();

    // Prologue: indices + packed interpolation weights for all (p, b).
    for (int i = t; i < PDIM * BT; i += 512) {
        int p = i >> 5;        // /32
        int b = i & 31;
        float v1 = x[(size_t)(2 * p) * BATCH + b0 + b];
        float v2 = x[(size_t)(2 * p + 1) * BATCH + b0 + b];

        float e1 = expf(-fabsf(v1));
        float c1 = (v1 > 0.f) ? (1.f - 0.5f * e1) : (0.5f * e1);
        int i1 = (int)(c1 * (float)GRIDS);
        i1 = i1 < 0 ? 0 : (i1 > GRIDS - 1 ? GRIDS - 1 : i1);

        float e2 = expf(-fabsf(v2));
        float c2 = (v2 > 0.f) ? (1.f - 0.5f * e2) : (0.5f * e2);
        int i2 = (int)(c2 * (float)GRIDS);
        i2 = i2 < 0 ? 0 : (i2 > GRIDS - 1 ? GRIDS - 1 : i2);

        float d1 = (v1 - sb[i1]) * sl[i1];
        float d2 = (v2 - sb[i2]) * sl[i2];
        float w11 = d1 * d2;
        float w10 = d1 - w11;
        float w01 = d2 - w11;
        float w00 = 1.f - d1 - w01;

        s_cell[p][b] = i1 * GP + i2;
        __half2 hA = __floats2half2_rn(w00, w01);   // lanes: (w00, w01)
        __half2 hB = __floats2half2_rn(w10, w11);   // lanes: (w10, w11)
        uint2 wq;
        wq.x = *reinterpret_cast<unsigned*>(&hA);
        wq.y = *reinterpret_cast<unsigned*>(&hB);
        s_wq[p][b] = wq;
    }
    __syncthreads();

    float acc[8] = {0.f, 0.f, 0.f, 0.f, 0.f, 0.f, 0.f, 0.f};
    const __half* __restrict__ tab = g_fpt;
    const int oofs = og * 8;

    for (int pg = 0; pg < PDIM / 4; ++pg) {
        __half2 hacc[4];
#pragma unroll
        for (int q = 0; q < 4; ++q) {
            const int p = pg * 4 + q;
            const int   c  = s_cell[p][bi];
            const uint2 wq = s_wq[p][bi];
            const __half2 hA = *reinterpret_cast<const __half2*>(&wq.x);
            const __half2 hB = *reinterpret_cast<const __half2*>(&wq.y);
            const __half2 h00 = __half2half2(__low2half(hA));
            const __half2 h01 = __half2half2(__high2half(hA));
            const __half2 h10 = __half2half2(__low2half(hB));
            const __half2 h11 = __half2half2(__high2half(hB));

            const __half* base = tab + ((size_t)p * CELLS + c) * ODIM + oofs;
            uint4 a0 = *reinterpret_cast<const uint4*>(base);                   // (i1,   i2  )
            uint4 a1 = *reinterpret_cast<const uint4*>(base + ODIM);            // (i1,   i2+1)
            uint4 a2 = *reinterpret_cast<const uint4*>(base + GP * ODIM);       // (i1+1, i2  )
            uint4 a3 = *reinterpret_cast<const uint4*>(base + (GP + 1) * ODIM); // (i1+1, i2+1)

            const unsigned* u0 = &a0.x;
            const unsigned* u1 = &a1.x;
            const unsigned* u2 = &a2.x;
            const unsigned* u3 = &a3.x;
#pragma unroll
            for (int j = 0; j < 4; ++j) {
                __half2 v0 = *reinterpret_cast<const __half2*>(&u0[j]);
                __half2 v1 = *reinterpret_cast<const __half2*>(&u1[j]);
                __half2 v2 = *reinterpret_cast<const __half2*>(&u2[j]);
                __half2 v3 = *reinterpret_cast<const __half2*>(&u3[j]);
                __half2 s = __hmul2(h00, v0);
                s = __hfma2(h01, v1, s);
                s = __hfma2(h10, v2, s);
                s = __hfma2(h11, v3, s);
                if (q == 0) hacc[j] = s;
                else        hacc[j] = __hadd2(hacc[j], s);
            }
        }
#pragma unroll
        for (int j = 0; j < 4; ++j) {
            float2 f = __half22float2(hacc[j]);
            acc[2 * j]     += f.x;
            acc[2 * j + 1] += f.y;
        }
    }

    // Epilogue: transpose through smem for coalesced 128B row stores.
    __syncthreads();
#pragma unroll
    for (int k = 0; k < 8; ++k) so[oofs + k][bi] = acc[k];
    __syncthreads();
    for (int idx = t; idx < ODIM * BT; idx += 512) {
        int o = idx >> 5;   // /32
        int j = idx & 31;
        out[(size_t)o * BATCH + b0 + j] = so[o][j];
    }
}

extern "C" void kernel_launch(void* const* d_in, const int* in_sizes, int n_in,
                              void* d_out, int out_size) {
    const float* x       = (const float*)d_in[0];
    const float* fp      = (const float*)d_in[1];
    const float* borders = (const float*)d_in[2];
    const float* invlen  = (const float*)d_in[3];
    float* out = (float*)d_out;

    kan_transpose<<<CELLS, 256>>>(fp);
    kan_main<<<BATCH / BT, 512>>>(x, borders, invlen, out);
}

// round 8
// speedup vs baseline: 1.2588x; 1.0414x over previous
#include <cuda_runtime.h>
#include <cuda_fp16.h>
#include <cstdint>

#define GRIDS 64
#define GP    65            // GRIDS + 1
#define ODIM  128
#define PDIM  64            // INPUT_DIM / 2
#define BATCH 16384
#define CELLS (GP * GP)     // 4225
#define BT    32            // batch tile per block

// fp16 transposed table: fp_t[p][cell][o], cell = ia*65 + ib
__device__ __half g_fpt[(size_t)PDIM * CELLS * ODIM];   // ~69 MB

// ---------------------------------------------------------------------------
// Kernel 1: transpose + fp32->fp16 convert (exact R6 version, 40.5us).
// ---------------------------------------------------------------------------
__global__ __launch_bounds__(256) void kan_transpose(const float* __restrict__ fp) {
    __shared__ float tile[ODIM * (PDIM + 1)];   // [o][p], pad 65
    const int cell = blockIdx.x;
    const float4* src = reinterpret_cast<const float4*>(fp + (size_t)cell * (ODIM * PDIM));

    for (int idx = threadIdx.x; idx < (ODIM * PDIM) / 4; idx += 256) {
        int o  = idx >> 4;
        int p4 = (idx & 15) << 2;
        float4 v = src[idx];
        float* row = &tile[o * (PDIM + 1) + p4];
        row[0] = v.x; row[1] = v.y; row[2] = v.z; row[3] = v.w;
    }
    __syncthreads();

    __half2* dst2 = reinterpret_cast<__half2*>(g_fpt);
    for (int idx = threadIdx.x; idx < (ODIM * PDIM) / 2; idx += 256) {
        int p  = idx >> 6;
        int o2 = idx & 63;
        float lo = tile[(2 * o2) * (PDIM + 1) + p];
        float hi = tile[(2 * o2 + 1) * (PDIM + 1) + p];
        dst2[((size_t)p * CELLS + cell) * (ODIM / 2) + o2] =
            __floats2half2_rn(lo, hi);
    }
}

// ---------------------------------------------------------------------------
// Kernel 2: main gather + bilinear reduction.
// Block: 512 threads = 16 o-groups (8 outputs each) x 32 batch columns.
// Weights stored pre-broadcast (4 x half2 duplicated) -> one LDS.128/iter.
// 16 groups of 4 p-iterations accumulate in half2, flush to fp32 per group.
// ---------------------------------------------------------------------------
__global__ __launch_bounds__(512, 2) void kan_main(const float* __restrict__ x,
                                                   const float* __restrict__ borders,
                                                   const float* __restrict__ invlen,
                                                   float* __restrict__ out) {
    __shared__ float sb[GP];
    __shared__ float sl[GRIDS];
    __shared__ int   s_cell[PDIM][BT];
    __shared__ uint4 s_wq[PDIM][BT];     // pre-broadcast half2 weights (w00,w01,w10,w11)
    __shared__ float so[ODIM][BT + 1];   // epilogue transpose buffer

    const int t  = threadIdx.x;
    const int og = t & 15;     // o-group: owns outputs og*8 .. og*8+7
    const int bi = t >> 4;     // batch index within tile, 0..31
    const int b0 = blockIdx.x * BT;

    if (t < GP)                 sb[t] = borders[t];
    else if (t < GP + GRIDS)    sl[t - GP] = invlen[t - GP];
    __syncthreads();

    // Prologue: indices + pre-broadcast packed weights for all (p, b).
    for (int i = t; i < PDIM * BT; i += 512) {
        int p = i >> 5;        // /32
        int b = i & 31;
        float v1 = x[(size_t)(2 * p) * BATCH + b0 + b];
        float v2 = x[(size_t)(2 * p + 1) * BATCH + b0 + b];

        float e1 = expf(-fabsf(v1));
        float c1 = (v1 > 0.f) ? (1.f - 0.5f * e1) : (0.5f * e1);
        int i1 = (int)(c1 * (float)GRIDS);
        i1 = i1 < 0 ? 0 : (i1 > GRIDS - 1 ? GRIDS - 1 : i1);

        float e2 = expf(-fabsf(v2));
        float c2 = (v2 > 0.f) ? (1.f - 0.5f * e2) : (0.5f * e2);
        int i2 = (int)(c2 * (float)GRIDS);
        i2 = i2 < 0 ? 0 : (i2 > GRIDS - 1 ? GRIDS - 1 : i2);

        float d1 = (v1 - sb[i1]) * sl[i1];
        float d2 = (v2 - sb[i2]) * sl[i2];
        float w11 = d1 * d2;
        float w10 = d1 - w11;
        float w01 = d2 - w11;
        float w00 = 1.f - d1 - w01;

        s_cell[p][b] = i1 * GP + i2;
        __half2 h00 = __float2half2_rn(w00);
        __half2 h01 = __float2half2_rn(w01);
        __half2 h10 = __float2half2_rn(w10);
        __half2 h11 = __float2half2_rn(w11);
        uint4 wq;
        wq.x = *reinterpret_cast<unsigned*>(&h00);
        wq.y = *reinterpret_cast<unsigned*>(&h01);
        wq.z = *reinterpret_cast<unsigned*>(&h10);
        wq.w = *reinterpret_cast<unsigned*>(&h11);
        s_wq[p][b] = wq;
    }
    __syncthreads();

    float acc[8] = {0.f, 0.f, 0.f, 0.f, 0.f, 0.f, 0.f, 0.f};
    const __half* __restrict__ tab = g_fpt;
    const int oofs = og * 8;

    for (int pg = 0; pg < PDIM / 4; ++pg) {
        __half2 hacc[4];
#pragma unroll
        for (int q = 0; q < 4; ++q) {
            const int p = pg * 4 + q;
            const int   c  = s_cell[p][bi];
            const uint4 wq = s_wq[p][bi];
            const __half2 h00 = *reinterpret_cast<const __half2*>(&wq.x);
            const __half2 h01 = *reinterpret_cast<const __half2*>(&wq.y);
            const __half2 h10 = *reinterpret_cast<const __half2*>(&wq.z);
            const __half2 h11 = *reinterpret_cast<const __half2*>(&wq.w);

            const __half* base = tab + ((size_t)p * CELLS + c) * ODIM + oofs;
            uint4 a0 = *reinterpret_cast<const uint4*>(base);                   // (i1,   i2  )
            uint4 a1 = *reinterpret_cast<const uint4*>(base + ODIM);            // (i1,   i2+1)
            uint4 a2 = *reinterpret_cast<const uint4*>(base + GP * ODIM);       // (i1+1, i2  )
            uint4 a3 = *reinterpret_cast<const uint4*>(base + (GP + 1) * ODIM); // (i1+1, i2+1)

            const unsigned* u0 = &a0.x;
            const unsigned* u1 = &a1.x;
            const unsigned* u2 = &a2.x;
            const unsigned* u3 = &a3.x;
#pragma unroll
            for (int j = 0; j < 4; ++j) {
                __half2 v0 = *reinterpret_cast<const __half2*>(&u0[j]);
                __half2 v1 = *reinterpret_cast<const __half2*>(&u1[j]);
                __half2 v2 = *reinterpret_cast<const __half2*>(&u2[j]);
                __half2 v3 = *reinterpret_cast<const __half2*>(&u3[j]);
                __half2 s = __hmul2(h00, v0);
                s = __hfma2(h01, v1, s);
                s = __hfma2(h10, v2, s);
                s = __hfma2(h11, v3, s);
                if (q == 0) hacc[j] = s;
                else        hacc[j] = __hadd2(hacc[j], s);
            }
        }
#pragma unroll
        for (int j = 0; j < 4; ++j) {
            float2 f = __half22float2(hacc[j]);
            acc[2 * j]     += f.x;
            acc[2 * j + 1] += f.y;
        }
    }

    // Epilogue: transpose through smem for coalesced 128B row stores.
    __syncthreads();
#pragma unroll
    for (int k = 0; k < 8; ++k) so[oofs + k][bi] = acc[k];
    __syncthreads();
    for (int idx = t; idx < ODIM * BT; idx += 512) {
        int o = idx >> 5;   // /32
        int j = idx & 31;
        out[(size_t)o * BATCH + b0 + j] = so[o][j];
    }
}

extern "C" void kernel_launch(void* const* d_in, const int* in_sizes, int n_in,
                              void* d_out, int out_size) {
    const float* x       = (const float*)d_in[0];
    const float* fp      = (const float*)d_in[1];
    const float* borders = (const float*)d_in[2];
    const float* invlen  = (const float*)d_in[3];
    float* out = (float*)d_out;

    kan_transpose<<<CELLS, 256>>>(fp);
    kan_main<<<BATCH / BT, 512>>>(x, borders, invlen, out);
}